// round 15
// baseline (speedup 1.0000x reference)
#include <cuda_runtime.h>
#include <cuda_bf16.h>
#include <cstddef>
#include <cstdint>

// Problem constants
#define NB    2
#define SLEN  2048
#define EMB   1024            // H=16, D=64
#define CPN   256             // chunks per batch (8 rows each)

// Scratch (__device__ globals; no allocation)
__device__ __align__(32) float g_part[NB][CPN][EMB];  // partials (2 MB)
__device__ __align__(32) float g_t[NB][EMB];          // t = blockdiag(Wv) @ sv
__device__ __align__(32) float g_y[NB][EMB];          // y = Wo @ t + bo

// ---- 256-bit vector memory ops (Blackwell) --------------------------------
__device__ __forceinline__ void ldg8_nc(const float* g, float4& a, float4& b) {
    asm volatile("ld.global.nc.v8.f32 {%0,%1,%2,%3,%4,%5,%6,%7}, [%8];"
                 : "=f"(a.x), "=f"(a.y), "=f"(a.z), "=f"(a.w),
                   "=f"(b.x), "=f"(b.y), "=f"(b.z), "=f"(b.w)
                 : "l"(g));
}
__device__ __forceinline__ void ldg8(const float* g, float4& a, float4& b) {
    asm volatile("ld.global.v8.f32 {%0,%1,%2,%3,%4,%5,%6,%7}, [%8];"
                 : "=f"(a.x), "=f"(a.y), "=f"(a.z), "=f"(a.w),
                   "=f"(b.x), "=f"(b.y), "=f"(b.z), "=f"(b.w)
                 : "l"(g));
}
__device__ __forceinline__ void stg8_cs(float* g, const float4& a, const float4& b) {
    asm volatile("st.global.cs.v8.f32 [%0], {%1,%2,%3,%4,%5,%6,%7,%8};"
                 :: "l"(g), "f"(a.x), "f"(a.y), "f"(a.z), "f"(a.w),
                    "f"(b.x), "f"(b.y), "f"(b.z), "f"(b.w) : "memory");
}

// ---------------------------------------------------------------------------
// K1: column-sum partials. Grid 512 x 256t. Block b: batch n = b>>8, chunk
// c = b&255 (8 rows). thread (rowgroup rg = t>>7, lane8 = t&127): sums 4 rows
// with LDG.256; rowgroups combined in smem; 128 threads write the partial.
// ---------------------------------------------------------------------------
__global__ void __launch_bounds__(256) k1_partials(const float* __restrict__ vals)
{
    __shared__ __align__(32) float4 sA[256], sB[256];

    const int n     = blockIdx.x >> 8;
    const int c     = blockIdx.x & 255;
    const int rg    = threadIdx.x >> 7;   // 0..1 (4 rows each)
    const int lane8 = threadIdx.x & 127;

    const float* __restrict__ base =
        vals + ((size_t)n * SLEN + (size_t)c * 8 + rg * 4) * EMB + lane8 * 8;

    float4 aA = make_float4(0.f, 0.f, 0.f, 0.f);
    float4 aB = make_float4(0.f, 0.f, 0.f, 0.f);
    #pragma unroll
    for (int s = 0; s < 4; ++s) {
        float4 vA, vB;
        ldg8_nc(base + s * EMB, vA, vB);
        aA.x += vA.x; aA.y += vA.y; aA.z += vA.z; aA.w += vA.w;
        aB.x += vB.x; aB.y += vB.y; aB.z += vB.z; aB.w += vB.w;
    }
    sA[threadIdx.x] = aA; sB[threadIdx.x] = aB;
    __syncthreads();
    if (rg == 0) {
        const float4 cA = sA[threadIdx.x + 128], cB = sB[threadIdx.x + 128];
        aA.x += cA.x; aA.y += cA.y; aA.z += cA.z; aA.w += cA.w;
        aB.x += cB.x; aB.y += cB.y; aB.z += cB.z; aB.w += cB.w;
        float4* dst = (float4*)&g_part[n][c][lane8 * 8];
        dst[0] = aA; dst[1] = aB;
    }
}

// ---------------------------------------------------------------------------
// K2: partials -> sv -> t. Grid 32 x 256t: block = (n = b>>4, head h = b&15).
// 16 c-splits (16 chunks each) x 16 float4 cols; fixed-pairing smem tree
// (deterministic); then 64-thread Wv matvec for this head.
// ---------------------------------------------------------------------------
__global__ void __launch_bounds__(256) k2_sv_wv(const float* __restrict__ Wv)
{
    __shared__ __align__(16) float4 sp[256];

    const int n  = blockIdx.x >> 4;
    const int h  = blockIdx.x & 15;
    const int L  = threadIdx.x & 15;     // float4 col within the head
    const int cs = threadIdx.x >> 4;     // 0..15 c-split (16 chunks each)

    float4 p = make_float4(0.f, 0.f, 0.f, 0.f);
    #pragma unroll
    for (int k = 0; k < 16; ++k) {
        const int c = cs * 16 + k;
        float4 v = __ldcg(&((const float4*)g_part[n][c])[h * 16 + L]);
        p.x += v.x; p.y += v.y; p.z += v.z; p.w += v.w;
    }
    sp[cs * 16 + L] = p;
    __syncthreads();
    #pragma unroll
    for (int st = 8; st >= 1; st >>= 1) {
        if (cs < st) {
            float4 a = sp[cs * 16 + L], d2 = sp[(cs + st) * 16 + L];
            a.x += d2.x; a.y += d2.y; a.z += d2.z; a.w += d2.w;
            sp[cs * 16 + L] = a;
        }
        __syncthreads();
    }
    if (threadIdx.x < 64) {
        const float* __restrict__ svh  = (const float*)sp;   // 64 floats
        const float* __restrict__ wrow = Wv + threadIdx.x * 64;
        float acc = 0.f;
        #pragma unroll 16
        for (int dp = 0; dp < 64; ++dp) acc += __ldg(&wrow[dp]) * svh[dp];
        g_t[n][h * 64 + threadIdx.x] = acc;
    }
}

// ---------------------------------------------------------------------------
// K3: y = Wo @ t + bo for both batches. Grid 128 x 256t: one warp per output
// element e = b*8 + warp; lanes stride the 4 KB Wo row with float4.
// ---------------------------------------------------------------------------
__global__ void __launch_bounds__(256) k3_y(const float* __restrict__ Wo,
                                            const float* __restrict__ bo)
{
    const int e    = blockIdx.x * 8 + (threadIdx.x >> 5);
    const int lane = threadIdx.x & 31;

    const float4* __restrict__ row = (const float4*)(Wo + (size_t)e * EMB);
    const float4* __restrict__ t0  = (const float4*)g_t[0];
    const float4* __restrict__ t1  = (const float4*)g_t[1];

    float a0 = 0.f, a1 = 0.f;
    #pragma unroll
    for (int i = lane; i < EMB / 4; i += 32) {
        float4 w = __ldg(&row[i]);
        float4 x = __ldcg(&t0[i]);
        float4 z = __ldcg(&t1[i]);
        a0 += w.x * x.x + w.y * x.y + w.z * x.z + w.w * x.w;
        a1 += w.x * z.x + w.y * z.y + w.z * z.z + w.w * z.w;
    }
    #pragma unroll
    for (int o = 16; o; o >>= 1) {
        a0 += __shfl_xor_sync(0xFFFFFFFFu, a0, o);
        a1 += __shfl_xor_sync(0xFFFFFFFFu, a1, o);
    }
    if (lane == 0) {
        const float be = __ldg(&bo[e]);
        g_y[0][e] = a0 + be;
        g_y[1][e] = a1 + be;
    }
}

// ---------------------------------------------------------------------------
// K4: broadcast y to all rows. Grid 512 x 256t. Block b: batch n = b>>8,
// 8-row slab c = b&255. thread (rg = t>>7, lane8 = t&127) stores 4 rows
// with STG.256 (evict-first).
// ---------------------------------------------------------------------------
__global__ void __launch_bounds__(256) k4_bcast(float* __restrict__ out)
{
    const int n     = blockIdx.x >> 8;
    const int c     = blockIdx.x & 255;
    const int rg    = threadIdx.x >> 7;
    const int lane8 = threadIdx.x & 127;

    float4 yA, yB;
    ldg8(&g_y[n][lane8 * 8], yA, yB);

    float* __restrict__ dst =
        out + ((size_t)n * SLEN + (size_t)c * 8 + rg * 4) * EMB + lane8 * 8;
    #pragma unroll
    for (int s = 0; s < 4; ++s)
        stg8_cs(dst + s * EMB, yA, yB);
}

// ---------------------------------------------------------------------------
// Inputs (metadata order): 0=values 1=keys 2=queries 3=mask 4=Wv 5=Wk 6=Wq
//                          7=Wo 8=bo.   Output: float32 [2, 2048, 1024].
// ---------------------------------------------------------------------------
extern "C" void kernel_launch(void* const* d_in, const int* in_sizes, int n_in,
                              void* d_out, int out_size)
{
    const float* values = (const float*)d_in[0];
    const float* Wv     = (const float*)d_in[4];
    const float* Wo     = (const float*)d_in[7];
    const float* bo     = (const float*)d_in[8];
    float*       out    = (float*)d_out;

    k1_partials<<<NB * CPN, 256>>>(values);
    k2_sv_wv<<<32, 256>>>(Wv);
    k3_y<<<128, 256>>>(Wo, bo);
    k4_bcast<<<NB * CPN, 256>>>(out);
}

// round 16
// speedup vs baseline: 1.0013x; 1.0013x over previous
#include <cuda_runtime.h>
#include <cuda_bf16.h>
#include <cstddef>
#include <cstdint>

// Problem constants
#define NB    2
#define SLEN  2048
#define EMB   1024            // H=16, D=64
#define NBLK  128             // persistent grid: 1 block/SM
#define THR   1024
#define CPN   64              // partial chunks per batch (32 rows each)
#define WO_BYTES 131072       // 32 Wo rows per block
#define SMEM_DYN (WO_BYTES)   // dynamic smem: Wo slab

// Scratch (__device__ globals; no allocation).
__device__ __align__(16) float g_part[NB][CPN][EMB];  // partials (512 KB)
__device__ __align__(16) float g_t[NB][EMB];          // t = blockdiag(Wv) @ sv
__device__ int   g_cnt[2];            // sense-reversing: self-resetting
__device__ volatile int g_flag[2];    // toggling -> replay-safe, no cleanup

// ---- cp.async helpers ------------------------------------------------------
__device__ __forceinline__ void cp_async16(uint32_t saddr, const void* gaddr) {
    asm volatile("cp.async.cg.shared.global [%0], [%1], 16;"
                 :: "r"(saddr), "l"(gaddr) : "memory");
}
__device__ __forceinline__ void cp_async_commit() {
    asm volatile("cp.async.commit_group;" ::: "memory");
}
__device__ __forceinline__ void cp_async_wait0() {
    asm volatile("cp.async.wait_group 0;" ::: "memory");
}

// Sense-reversing grid barrier: counter self-resets, flag toggles.
__device__ __forceinline__ void gbar(int k)
{
    __syncthreads();
    if (threadIdx.x == 0) {
        const int old = g_flag[k];
        __threadfence();
        if (atomicAdd(&g_cnt[k], 1) == NBLK - 1) {
            g_cnt[k] = 0;
            __threadfence();
            g_flag[k] = old ^ 1;
        } else {
            while (g_flag[k] == old) {}
        }
        __threadfence();
    }
    __syncthreads();
}

__global__ void __launch_bounds__(THR, 1)
k_fused(const float* __restrict__ vals,
        const float* __restrict__ Wv,
        const float* __restrict__ Wo,
        const float* __restrict__ bo,
        float*       __restrict__ out)
{
    extern __shared__ __align__(16) float4 s_wo[];  // 128 KB: 32 Wo rows
    __shared__ __align__(16) float4 s_red[1024];    // 16 KB: P1 combine / P2 tree
    __shared__ __align__(16) float4 s_t[256];       //  4 KB: t[n] for this block
    __shared__ __align__(16) float4 s_y[8];         // 32 y values

    const int b   = blockIdx.x;
    const int tid = threadIdx.x;
    const uint32_t swo = (uint32_t)__cvta_generic_to_shared(s_wo);

    // Output-slab identity: eslab = b>>2 (32 cols), n2 = (b>>1)&1, rg = b&1
    const int eslab = b >> 2;
    const int n2    = (b >> 1) & 1;
    const int rg    = b & 1;

    // ======================= P1: column-sum partials =======================
    // Block b: batch n = b>>6, 32-row slab c = b&63. 4 rowgroups x 256 cols,
    // 8 rows per thread (MLP=8); smem combine -> one 4 KB partial.
    {
        const int n   = b >> 6;
        const int c   = b & 63;
        const int prg = tid >> 8;      // rowgroup 0..3
        const int col = tid & 255;

        const float4* __restrict__ base =
            (const float4*)(vals + (size_t)(n * SLEN + c * 32 + prg * 8) * EMB);

        float4 acc = make_float4(0.f, 0.f, 0.f, 0.f);
        #pragma unroll
        for (int s = 0; s < 8; ++s) {
            float4 v = __ldg(&base[s * (EMB / 4) + col]);
            acc.x += v.x; acc.y += v.y; acc.z += v.z; acc.w += v.w;
        }
        s_red[tid] = acc;
        __syncthreads();
        if (tid < 256) {
            float4 a0 = s_red[tid];
            const float4 a1 = s_red[256 + tid];
            const float4 a2 = s_red[512 + tid];
            const float4 a3 = s_red[768 + tid];
            a0.x = (a0.x + a1.x) + (a2.x + a3.x);
            a0.y = (a0.y + a1.y) + (a2.y + a3.y);
            a0.z = (a0.z + a1.z) + (a2.z + a3.z);
            a0.w = (a0.w + a1.w) + (a2.w + a3.w);
            ((float4*)g_part[n][c])[tid] = a0;
        }
    }

    // Prefetch this block's 32 Wo rows (128 KB) into smem: 8 x cp.async16
    // per thread. Issued before bar1 -> overlaps barrier + P2 dead time.
    {
        const float4* __restrict__ wsrc =
            (const float4*)(Wo + (size_t)eslab * 32 * EMB);
        #pragma unroll
        for (int j = 0; j < 8; ++j) {
            const int idx = tid + j * 1024;          // 0..8191 float4s
            cp_async16(swo + (uint32_t)idx * 16, wsrc + idx);
        }
        cp_async_commit();
    }

    gbar(0);    // all partials visible

    // ================= P2 (32 blocks): partials -> sv -> t =================
    // Block (n = b>>4, head h = b&15). 1024 threads = 64 chunks x 16 cols;
    // fixed-pairing tree; then 64-thread Wv matvec.
    if (b < 32) {
        const int n = b >> 4;
        const int h = b & 15;
        const int c = tid >> 4;        // chunk 0..63
        const int L = tid & 15;        // float4 col within the head

        s_red[c * 16 + L] = __ldcg(&((const float4*)g_part[n][c])[h * 16 + L]);
        __syncthreads();
        #pragma unroll
        for (int st = 32; st >= 1; st >>= 1) {
            if (c < st) {
                float4 a = s_red[c * 16 + L], d2 = s_red[(c + st) * 16 + L];
                a.x += d2.x; a.y += d2.y; a.z += d2.z; a.w += d2.w;
                s_red[c * 16 + L] = a;
            }
            __syncthreads();
        }
        if (tid < 64) {
            const float* __restrict__ svh  = (const float*)s_red;  // 64 floats
            const float* __restrict__ wrow = Wv + tid * 64;
            float acc = 0.f;
            #pragma unroll 16
            for (int dp = 0; dp < 64; ++dp) acc += __ldg(&wrow[dp]) * svh[dp];
            g_t[n][h * 64 + tid] = acc;
        }
    }

    gbar(1);    // t visible

    // ============== P3 (local): y[eslab*32..+32) for batch n2 ==============
    if (tid < 256) s_t[tid] = __ldcg(&((const float4*)g_t[n2])[tid]);
    cp_async_wait0();                   // Wo slab resident
    __syncthreads();
    {
        const int w    = tid >> 5;      // warp 0..31 -> one e each
        const int lane = tid & 31;
        // lane covers 8 CONSECUTIVE float4s (conflict-free LDS)
        const float4* __restrict__ wrow = s_wo + w * 256 + lane * 8;
        const float4* __restrict__ tv   = s_t + lane * 8;

        float acc = 0.f;
        #pragma unroll
        for (int j = 0; j < 8; ++j) {
            const float4 a = wrow[j];
            const float4 x = tv[j];
            acc += a.x * x.x + a.y * x.y + a.z * x.z + a.w * x.w;
        }
        #pragma unroll
        for (int o = 16; o; o >>= 1) acc += __shfl_xor_sync(0xFFFFFFFFu, acc, o);
        if (lane == 0) ((float*)s_y)[w] = acc + __ldg(&bo[eslab * 32 + w]);
    }
    __syncthreads();

    // ========= P4 (no barrier!): store the 32-col slab to 1024 rows =========
    // thread = (row-within-group r = tid>>3, seg = tid&7); 8 iterations of
    // 128 rows. Each lane-octet writes one contiguous 128 B row segment.
    {
        const int seg = tid & 7;
        const int r0  = tid >> 3;              // 0..127
        const float4 v = s_y[seg];

        float4* __restrict__ o4 =
            (float4*)(out + ((size_t)n2 * SLEN + (size_t)rg * 1024) * EMB
                          + eslab * 32) + seg;
        #pragma unroll
        for (int it = 0; it < 8; ++it) {
            const size_t row = (size_t)it * 128 + r0;
            o4[row * (EMB / 4)] = v;
        }
    }
    // no exit barrier, no state reset needed (sense-reversing barriers)
}

// ---------------------------------------------------------------------------
// Inputs (metadata order): 0=values 1=keys 2=queries 3=mask 4=Wv 5=Wk 6=Wq
//                          7=Wo 8=bo.   Output: float32 [2, 2048, 1024].
// ---------------------------------------------------------------------------
extern "C" void kernel_launch(void* const* d_in, const int* in_sizes, int n_in,
                              void* d_out, int out_size)
{
    const float* values = (const float*)d_in[0];
    const float* Wv     = (const float*)d_in[4];
    const float* Wo     = (const float*)d_in[7];
    const float* bo     = (const float*)d_in[8];
    float*       out    = (float*)d_out;

    cudaFuncSetAttribute(k_fused, cudaFuncAttributeMaxDynamicSharedMemorySize,
                         SMEM_DYN);
    k_fused<<<NBLK, THR, SMEM_DYN>>>(values, Wv, Wo, bo, out);
}

// round 17
// speedup vs baseline: 1.1946x; 1.1931x over previous
#include <cuda_runtime.h>
#include <cuda_bf16.h>
#include <cstddef>
#include <cstdint>

// Problem constants
#define NB    2
#define SLEN  2048
#define EMB   1024            // H=16, D=64
#define NBLK  256             // persistent grid (co-resident: 148 SMs x 2)
#define THR   512
#define CPN   256             // partial chunks per batch (8 rows each)
#define RPB   8               // rows per partial chunk

// Scratch (__device__ globals; no allocation). Counters self-reset at full
// arrival; epochs are monotonic (read at entry, compared) -> NO cleanup
// phase and NO exit barrier needed. Replay-safe by construction.
__device__ __align__(16) float g_part[NB][CPN][EMB];  // partials (2 MB)
__device__ __align__(16) float g_t[NB][EMB];
__device__ __align__(16) float g_y[NB][EMB];
__device__ int g_c1, g_c2, g_c3;            // arrival counters (self-reset)
__device__ volatile int g_e1, g_e2, g_e3;   // epochs (monotonic)

// ---- cp.async helpers ------------------------------------------------------
__device__ __forceinline__ void cp_async16(uint32_t saddr, const void* gaddr) {
    asm volatile("cp.async.cg.shared.global [%0], [%1], 16;"
                 :: "r"(saddr), "l"(gaddr) : "memory");
}
__device__ __forceinline__ void cp_async_commit() {
    asm volatile("cp.async.commit_group;" ::: "memory");
}
__device__ __forceinline__ void cp_async_wait0() {
    asm volatile("cp.async.wait_group 0;" ::: "memory");
}

__global__ void __launch_bounds__(THR, 2)
k_fused(const float* __restrict__ vals,
        const float* __restrict__ Wv,
        const float* __restrict__ Wo,
        const float* __restrict__ bo,
        float*       __restrict__ out)
{
    const int b   = blockIdx.x;
    const int tid = threadIdx.x;

    __shared__ __align__(16) float4 s_wo[1024];   // 16 KB: 4 Wo rows
    __shared__ __align__(16) float4 s_p[512];     //  8 KB: P1/P2 scratch
    __shared__ float s_part3[NB][4][4];
    __shared__ int   s_e1, s_e2, s_e3;            // entry epoch snapshot

    const uint32_t swo = (uint32_t)__cvta_generic_to_shared(s_wo);

    // snapshot epochs BEFORE any arrival can happen this replay
    if (tid == 0) { s_e1 = g_e1; s_e2 = g_e2; s_e3 = g_e3; }
    __syncthreads();

    // ======================= P1: column-sum partials =======================
    // Block b: batch n = b>>7, chunks 2*(b&127)+{0,1}; halves of the block
    // each sum one 8-row chunk (MLP=8).
    {
        const int n   = b >> 7;
        const int c   = ((b & 127) << 1) + (tid >> 8);  // chunk 0..255
        const int col = tid & 255;                      // float4 lane
        const float4* __restrict__ base =
            (const float4*)(vals + (size_t)n * SLEN * EMB + (size_t)c * RPB * EMB);

        float4 acc = make_float4(0.f, 0.f, 0.f, 0.f);
        #pragma unroll
        for (int s = 0; s < RPB; ++s) {
            float4 v = __ldg(&base[s * (EMB / 4) + col]);
            acc.x += v.x; acc.y += v.y; acc.z += v.z; acc.w += v.w;
        }
        ((float4*)g_part[n][c])[col] = acc;
    }

    // ---- f1 arrive (non-blocking) + Wo prefetch overlapped with waits ----
    __syncthreads();
    {   // prefetch this block's 4 Wo rows (16 KB): 2 x 16 B per thread
        const float4* __restrict__ wsrc = (const float4*)(Wo + (size_t)b * 4 * EMB);
        cp_async16(swo + (uint32_t)tid * 16,         wsrc + tid);
        cp_async16(swo + (uint32_t)(tid + 512) * 16, wsrc + tid + 512);
        cp_async_commit();
    }
    if (tid == 0) {
        __threadfence();
        if (atomicAdd(&g_c1, 1) == NBLK - 1) {
            g_c1 = 0;                       // self-reset (all arrived)
            __threadfence();
            g_e1 = s_e1 + 1;                // release
        }
    }

    // ================= P2 (32 blocks): partials -> sv -> t =================
    // Block (n = b>>4, head h = b&15). 512 threads = 32 c-splits x 16 cols.
    if (b < 32) {
        if (tid == 0) {
            while (g_e1 == s_e1) {}
            __threadfence();
        }
        __syncthreads();

        const int n  = b >> 4;
        const int h  = b & 15;
        const int L  = tid & 15;       // float4 col within the head
        const int cs = tid >> 4;       // 0..31 c-split (8 chunks each)

        float4 p = make_float4(0.f, 0.f, 0.f, 0.f);
        #pragma unroll
        for (int k = 0; k < 8; ++k) {
            const int c = cs * 8 + k;
            float4 v = __ldcg(&((const float4*)g_part[n][c])[h * 16 + L]);
            p.x += v.x; p.y += v.y; p.z += v.z; p.w += v.w;
        }
        s_p[cs * 16 + L] = p;
        __syncthreads();
        #pragma unroll
        for (int st = 16; st >= 1; st >>= 1) {
            if (cs < st) {
                float4 a = s_p[cs * 16 + L], d2 = s_p[(cs + st) * 16 + L];
                a.x += d2.x; a.y += d2.y; a.z += d2.z; a.w += d2.w;
                s_p[cs * 16 + L] = a;
            }
            __syncthreads();
        }
        if (tid < 64) {
            const float* __restrict__ svh  = (const float*)s_p;    // 64 floats
            const float* __restrict__ wrow = Wv + tid * 64;
            float acc = 0.f;
            #pragma unroll 16
            for (int dp = 0; dp < 64; ++dp) acc += __ldg(&wrow[dp]) * svh[dp];
            g_t[n][h * 64 + tid] = acc;
        }
        __syncthreads();
        if (tid == 0) {
            __threadfence();
            if (atomicAdd(&g_c2, 1) == 31) {
                g_c2 = 0;
                __threadfence();
                g_e2 = s_e2 + 1;
            }
        }
    }

    // ---------------- all blocks: wait for t, Wo now in smem ----------------
    if (tid == 0) {
        while (g_e2 == s_e2) {}
        __threadfence();
    }
    __syncthreads();
    cp_async_wait0();
    __syncthreads();

    // ===== P3: y[4b..4b+4) = s_wo @ t + bo (both batches), Wo from SMEM =====
    {
        const int e0   = b * 4;
        const int w    = tid >> 5;       // warp 0..15
        const int lane = tid & 31;
        const int el   = w >> 2;         // e-local 0..3
        const int q    = w & 3;          // quarter (64 float4 each)

        const float4* __restrict__ worow = s_wo + el * 256 + q * 64;
        const float4* __restrict__ t0 = (const float4*)g_t[0] + q * 64;
        const float4* __restrict__ t1 = (const float4*)g_t[1] + q * 64;

        float a0 = 0.f, a1 = 0.f;
        #pragma unroll
        for (int i = lane; i < 64; i += 32) {
            float4 wv = worow[i];
            float4 x  = __ldcg(&t0[i]);
            float4 z  = __ldcg(&t1[i]);
            a0 += wv.x * x.x + wv.y * x.y + wv.z * x.z + wv.w * x.w;
            a1 += wv.x * z.x + wv.y * z.y + wv.z * z.z + wv.w * z.w;
        }
        #pragma unroll
        for (int o = 16; o; o >>= 1) {
            a0 += __shfl_xor_sync(0xFFFFFFFFu, a0, o);
            a1 += __shfl_xor_sync(0xFFFFFFFFu, a1, o);
        }
        if (lane == 0) {
            s_part3[0][el][q] = a0;
            s_part3[1][el][q] = a1;
        }
        __syncthreads();
        if (tid < 8) {                    // n = tid>>2, e-local = tid&3
            const int nn = tid >> 2;
            const int ee = tid & 3;
            g_y[nn][e0 + ee] = ((s_part3[nn][ee][0] + s_part3[nn][ee][1])
                              + (s_part3[nn][ee][2] + s_part3[nn][ee][3]))
                             + __ldg(&bo[e0 + ee]);
        }
    }

    // ------------------------------ f3 (full) ------------------------------
    __syncthreads();
    if (tid == 0) {
        __threadfence();
        if (atomicAdd(&g_c3, 1) == NBLK - 1) {
            g_c3 = 0;
            __threadfence();
            g_e3 = s_e3 + 1;
        } else {
            while (g_e3 == s_e3) {}
        }
        __threadfence();
    }
    __syncthreads();

    // ===================== P4: broadcast y to all rows =====================
    // Block b: batch n = b>>7, 16-row slab; halves write 8 rows each.
    // Plain float4 stores, full-row contiguous (proven fastest pattern).
    {
        const int n    = b >> 7;
        const int c    = b & 127;
        const int half = tid >> 8;
        const int col  = tid & 255;
        const float4 v = __ldcg(&((const float4*)g_y[n])[col]);

        float4* __restrict__ dst =
            (float4*)(out + (size_t)n * SLEN * EMB
                          + ((size_t)c * 16 + half * 8) * EMB);
        #pragma unroll
        for (int s = 0; s < 8; ++s)
            dst[s * (EMB / 4) + col] = v;
    }
    // no exit barrier, no state reset: epochs are monotonic, counters
    // self-reset at full arrival.
}

// ---------------------------------------------------------------------------
// Inputs (metadata order): 0=values 1=keys 2=queries 3=mask 4=Wv 5=Wk 6=Wq
//                          7=Wo 8=bo.   Output: float32 [2, 2048, 1024].
// ---------------------------------------------------------------------------
extern "C" void kernel_launch(void* const* d_in, const int* in_sizes, int n_in,
                              void* d_out, int out_size)
{
    const float* values = (const float*)d_in[0];
    const float* Wv     = (const float*)d_in[4];
    const float* Wo     = (const float*)d_in[7];
    const float* bo     = (const float*)d_in[8];
    float*       out    = (float*)d_out;

    k_fused<<<NBLK, THR>>>(values, Wv, Wo, bo, out);
}